// round 1
// baseline (speedup 1.0000x reference)
#include <cuda_runtime.h>

#define NMAX 100000
#define HDIM 64
#define NGROUP 8

// Scratch (device globals: no allocation allowed in kernel_launch)
__device__ __align__(16) float g_h[NMAX * HDIM];     // current node features
__device__ __align__(16) float g_num[NMAX * HDIM];   // unnormalized numerator accum
__device__ float g_s[NMAX];                          // h . a_src per node
__device__ float g_d[NMAX];                          // h . a_dst per node
__device__ float g_denom[NMAX];                      // softmax denominator accum
__device__ float g_vnsum[NGROUP * HDIM];             // global_add_pool accum

// ---------------------------------------------------------------------------
// Zero the accumulators used by the first edge pass + the vn pool.
// ---------------------------------------------------------------------------
__global__ void zero_kernel(int N) {
    int i = blockIdx.x * blockDim.x + threadIdx.x;
    int stride = gridDim.x * blockDim.x;
    int total = N * HDIM;
    for (int j = i; j < total; j += stride) g_num[j] = 0.f;
    for (int j = i; j < N; j += stride) g_denom[j] = 0.f;
    if (i < NGROUP * HDIM) g_vnsum[i] = 0.f;
}

// ---------------------------------------------------------------------------
// Layer 0 linear: h = x(N,3) @ W0(3,64); also s = h.as, d = h.ad
// Block = 64 nodes, 256 threads (c = t&63 column, r = t>>6).
// ---------------------------------------------------------------------------
__global__ void lin0_kernel(const float* __restrict__ x,
                            const float* __restrict__ W0,
                            const float* __restrict__ as0,
                            const float* __restrict__ ad0, int N) {
    __shared__ float Ws[3 * 64];
    __shared__ float hs[64][65];
    int t = threadIdx.x;
    int c = t & 63, r = t >> 6;
    int n0 = blockIdx.x * 64;
    if (t < 192) Ws[t] = W0[t];
    __syncthreads();
    #pragma unroll
    for (int i = 0; i < 16; i++) {
        int nl = r * 16 + i;
        int n = n0 + nl;
        float acc = 0.f;
        if (n < N) {
            float x0 = x[n * 3 + 0], x1 = x[n * 3 + 1], x2 = x[n * 3 + 2];
            acc = x0 * Ws[c] + x1 * Ws[64 + c] + x2 * Ws[128 + c];
            g_h[n * 64 + c] = acc;
        }
        hs[nl][c] = acc;
    }
    __syncthreads();
    if (t < 64) {
        int n = n0 + t;
        if (n < N) {
            float sv = 0.f, dv = 0.f;
            #pragma unroll
            for (int k = 0; k < 64; k++) {
                float hv = hs[t][k];
                sv += hv * as0[k];
                dv += hv * ad0[k];
            }
            g_s[n] = sv;
            g_d[n] = dv;
        }
    }
}

// ---------------------------------------------------------------------------
// Edge pass: for each edge (incl. implicit self loops at index >= E):
//   p = exp(leaky_relu_0.2(s[src] + d[dst]))      (max-shift skipped: softmax
//                                                  is shift invariant)
//   denom[dst] += p ; num[dst] += p * h[src]
// 16 lanes per edge, float4 gathers + red.global.add.v4.f32 scatters.
// ---------------------------------------------------------------------------
__global__ void edge_kernel(const int* __restrict__ ei, int E, int N) {
    long long gid = (long long)blockIdx.x * blockDim.x + threadIdx.x;
    int eidx = (int)(gid >> 4);
    int lane = (int)(gid & 15);
    if (eidx >= E + N) return;
    int srcn, dstn;
    if (eidx < E) {
        srcn = ei[eidx];
        dstn = ei[E + eidx];
    } else {
        srcn = dstn = eidx - E;
    }
    float lg = g_s[srcn] + g_d[dstn];
    lg = lg > 0.f ? lg : 0.2f * lg;
    float p = __expf(lg);
    if (lane == 0) atomicAdd(&g_denom[dstn], p);
    float4 hv = ((const float4*)(g_h + srcn * 64))[lane];
    float* dptr = g_num + dstn * 64 + lane * 4;
    asm volatile("red.global.add.v4.f32 [%0], {%1,%2,%3,%4};"
                 :: "l"(dptr), "f"(p * hv.x), "f"(p * hv.y),
                    "f"(p * hv.z), "f"(p * hv.w)
                 : "memory");
}

// ---------------------------------------------------------------------------
// Fused: prev-layer finalize (num/denom + b, LeakyReLU 0.01) -> next linear
// h = act_prev @ W (64x64), plus s/d dots; re-zeroes num/denom for next pass.
// Block = 64 nodes, 256 threads.
// ---------------------------------------------------------------------------
__global__ void fin_lin_kernel(const float* __restrict__ bprev,
                               const float* __restrict__ W,
                               const float* __restrict__ avs,
                               const float* __restrict__ avd, int N) {
    __shared__ float Ws[64][64];
    __shared__ float xs[64][65];  // reused as hs after GEMM
    int t = threadIdx.x;
    int c = t & 63, r = t >> 6;
    int n0 = blockIdx.x * 64;
    #pragma unroll
    for (int i = 0; i < 16; i++) {
        int k = r * 16 + i;
        Ws[k][c] = W[k * 64 + c];
    }
    #pragma unroll
    for (int i = 0; i < 16; i++) {
        int nl = r * 16 + i;
        int n = n0 + nl;
        float v = 0.f;
        if (n < N) {
            v = g_num[n * 64 + c] / g_denom[n] + bprev[c];
            v = v > 0.f ? v : 0.01f * v;
        }
        xs[nl][c] = v;
    }
    __syncthreads();
    // zero accumulators for the next edge pass (all reads of num/denom done)
    #pragma unroll
    for (int i = 0; i < 16; i++) {
        int n = n0 + r * 16 + i;
        if (n < N) {
            g_num[n * 64 + c] = 0.f;
            if (c == 0) g_denom[n] = 0.f;
        }
    }
    float acc[16];
    #pragma unroll
    for (int i = 0; i < 16; i++) acc[i] = 0.f;
    for (int k = 0; k < 64; k++) {
        float wv = Ws[k][c];
        #pragma unroll
        for (int i = 0; i < 16; i++) acc[i] += xs[r * 16 + i][k] * wv;
    }
    __syncthreads();  // all xs reads done
    #pragma unroll
    for (int i = 0; i < 16; i++) {
        int nl = r * 16 + i;
        int n = n0 + nl;
        if (n < N) g_h[n * 64 + c] = acc[i];
        xs[nl][c] = acc[i];
    }
    __syncthreads();
    if (t < 64) {
        int n = n0 + t;
        if (n < N) {
            float sv = 0.f, dv = 0.f;
            #pragma unroll
            for (int k = 0; k < 64; k++) {
                float hv = xs[t][k];
                sv += hv * avs[k];
                dv += hv * avd[k];
            }
            g_s[n] = sv;
            g_d[n] = dv;
        }
    }
}

// ---------------------------------------------------------------------------
// Final node stage: hfin = act(num/denom + b2); out1 = hfin @ out_w + out_b;
// vn pool: run-length segmented add (batch is sorted) into g_vnsum.
// ---------------------------------------------------------------------------
__global__ void fin_last_kernel(const float* __restrict__ b2,
                                const float* __restrict__ out_w,
                                const float* __restrict__ out_b,
                                const int* __restrict__ batch,
                                float* __restrict__ out1, int N) {
    __shared__ float hs[64][65];
    __shared__ float ow[64 * 20];
    __shared__ float ob[20];
    int t = threadIdx.x;
    int c = t & 63, r = t >> 6;
    int n0 = blockIdx.x * 64;
    for (int j = t; j < 64 * 20; j += 256) ow[j] = out_w[j];
    if (t < 20) ob[t] = out_b[t];
    #pragma unroll
    for (int i = 0; i < 16; i++) {
        int nl = r * 16 + i;
        int n = n0 + nl;
        float v = 0.f;
        if (n < N) {
            v = g_num[n * 64 + c] / g_denom[n] + b2[c];
            v = v > 0.f ? v : 0.01f * v;
        }
        hs[nl][c] = v;
    }
    __syncthreads();
    for (int j = t; j < 64 * 20; j += 256) {
        int nl = j / 20, oc = j % 20;
        int n = n0 + nl;
        if (n < N) {
            float a = ob[oc];
            #pragma unroll
            for (int k = 0; k < 64; k++) a += hs[nl][k] * ow[k * 20 + oc];
            out1[n * 20 + oc] = a;
        }
    }
    if (t < 64) {
        int nend = N - n0;
        if (nend > 64) nend = 64;
        int curg = batch[n0];
        float run = 0.f;
        for (int nl = 0; nl < nend; nl++) {
            int g = batch[n0 + nl];
            if (g != curg) {
                atomicAdd(&g_vnsum[curg * 64 + t], run);
                run = 0.f;
                curg = g;
            }
            run += hs[nl][t];
        }
        atomicAdd(&g_vnsum[curg * 64 + t], run);
    }
}

// ---------------------------------------------------------------------------
// Virtual-node MLP head: 4 layers on [8,64], last to [8,20]. One block.
// ---------------------------------------------------------------------------
__global__ void vn_mlp_kernel(const float* __restrict__ vn_emb0,
                              const float* __restrict__ w1, const float* __restrict__ bb1,
                              const float* __restrict__ w2, const float* __restrict__ bb2,
                              const float* __restrict__ w3, const float* __restrict__ bb3,
                              const float* __restrict__ w4, const float* __restrict__ bb4,
                              float* __restrict__ outvn) {
    __shared__ float a[NGROUP][64], tmp[NGROUP][64];
    int t = threadIdx.x;  // 512
    int g = t >> 6, c = t & 63;
    a[g][c] = g_vnsum[g * 64 + c] + vn_emb0[c];
    __syncthreads();
    float s = bb1[c];
    for (int k = 0; k < 64; k++) s += a[g][k] * w1[k * 64 + c];
    tmp[g][c] = fmaxf(s, 0.f);
    __syncthreads();
    s = bb2[c];
    for (int k = 0; k < 64; k++) s += tmp[g][k] * w2[k * 64 + c];
    a[g][c] = fmaxf(s, 0.f);
    __syncthreads();
    s = bb3[c];
    for (int k = 0; k < 64; k++) s += a[g][k] * w3[k * 64 + c];
    tmp[g][c] = fmaxf(s, 0.f);
    __syncthreads();
    if (c < 20) {
        s = bb4[c];
        for (int k = 0; k < 64; k++) s += tmp[g][k] * w4[k * 20 + c];
        outvn[g * 20 + c] = fmaxf(s, 0.f);
    }
}

// ---------------------------------------------------------------------------
extern "C" void kernel_launch(void* const* d_in, const int* in_sizes, int n_in,
                              void* d_out, int out_size) {
    const float* x      = (const float*)d_in[0];
    const int*   ei     = (const int*)d_in[1];
    const int*   batch  = (const int*)d_in[2];
    const float* W0     = (const float*)d_in[3];
    const float* as0    = (const float*)d_in[4];
    const float* ad0    = (const float*)d_in[5];
    const float* b0     = (const float*)d_in[6];
    const float* W1     = (const float*)d_in[7];
    const float* as1    = (const float*)d_in[8];
    const float* ad1    = (const float*)d_in[9];
    const float* b1     = (const float*)d_in[10];
    const float* W2     = (const float*)d_in[11];
    const float* as2    = (const float*)d_in[12];
    const float* ad2    = (const float*)d_in[13];
    const float* b2     = (const float*)d_in[14];
    const float* vn_emb0= (const float*)d_in[15];
    const float* m1_w1  = (const float*)d_in[16];
    const float* m1_b1  = (const float*)d_in[17];
    const float* m1_w2  = (const float*)d_in[18];
    const float* m1_b2  = (const float*)d_in[19];
    const float* mf_w1  = (const float*)d_in[20];
    const float* mf_b1  = (const float*)d_in[21];
    const float* mf_w2  = (const float*)d_in[22];
    const float* mf_b2  = (const float*)d_in[23];
    const float* out_w  = (const float*)d_in[24];
    const float* out_b  = (const float*)d_in[25];

    int N = in_sizes[0] / 3;
    int E = in_sizes[1] / 2;
    float* out1 = (float*)d_out;
    float* outvn = out1 + (long long)N * 20;

    int nblk = (N + 63) / 64;
    long long eth = (long long)(E + N) * 16;
    int eblk = (int)((eth + 255) / 256);

    zero_kernel<<<1024, 256>>>(N);
    lin0_kernel<<<nblk, 256>>>(x, W0, as0, ad0, N);
    edge_kernel<<<eblk, 256>>>(ei, E, N);
    fin_lin_kernel<<<nblk, 256>>>(b0, W1, as1, ad1, N);
    edge_kernel<<<eblk, 256>>>(ei, E, N);
    fin_lin_kernel<<<nblk, 256>>>(b1, W2, as2, ad2, N);
    edge_kernel<<<eblk, 256>>>(ei, E, N);
    fin_last_kernel<<<nblk, 256>>>(b2, out_w, out_b, batch, out1, N);
    vn_mlp_kernel<<<1, 512>>>(vn_emb0, m1_w1, m1_b1, m1_w2, m1_b2,
                              mf_w1, mf_b1, mf_w2, mf_b2, outvn);
}

// round 3
// speedup vs baseline: 1.7887x; 1.7887x over previous
#include <cuda_runtime.h>

#define NMAX 100000
#define EMAX 1600000
#define HDIM 64
#define NGROUP 8

// ---------------- device scratch (no allocation allowed) --------------------
__device__ __align__(16) float g_hA[NMAX * HDIM];
__device__ __align__(16) float g_hB[NMAX * HDIM];
__device__ float g_s[NMAX];
__device__ float g_d[NMAX];
__device__ int   g_cnt[NMAX + 1];     // histogram, later scatter cursor
__device__ int   g_offs[NMAX + 1];    // CSR row offsets (by dst)
__device__ int   g_blksum[256];
__device__ int   g_blkoff[256];
__device__ int   g_csr[EMAX];         // src indices sorted by dst
__device__ float g_vnsum[NGROUP * HDIM];

// ---------------------------------------------------------------------------
// CSR build: zero -> histogram -> scan(A,B,C) -> scatter
// ---------------------------------------------------------------------------
__global__ void zero_kernel(int N) {
    int i = blockIdx.x * blockDim.x + threadIdx.x;
    if (i <= N) g_cnt[i] = 0;
    if (i < NGROUP * HDIM) g_vnsum[i] = 0.f;
}

__global__ void hist_kernel(const int* __restrict__ ei, int E) {
    int e = blockIdx.x * blockDim.x + threadIdx.x;
    if (e < E) atomicAdd(&g_cnt[ei[E + e]], 1);
}

// per-block exclusive scan of g_cnt (1024 elements / block of 256 threads)
__global__ void scanA_kernel(int N) {
    __shared__ int wsum[8];
    int t = threadIdx.x;
    int base = blockIdx.x * 1024;
    int v[4]; int s = 0;
#pragma unroll
    for (int j = 0; j < 4; j++) {
        int idx = base + t * 4 + j;
        v[j] = (idx < N) ? g_cnt[idx] : 0;
        s += v[j];
    }
    int lane = t & 31, wid = t >> 5;
    int inc = s;
#pragma unroll
    for (int o = 1; o < 32; o <<= 1) {
        int y = __shfl_up_sync(0xffffffffu, inc, o);
        if (lane >= o) inc += y;
    }
    if (lane == 31) wsum[wid] = inc;
    __syncthreads();
    if (t < 8) {
        int x = wsum[t];
#pragma unroll
        for (int o = 1; o < 8; o <<= 1) {
            int y = __shfl_up_sync(0xffu, x, o);
            if (t >= o) x += y;
        }
        wsum[t] = x;
    }
    __syncthreads();
    int excl = inc - s + (wid > 0 ? wsum[wid - 1] : 0);
#pragma unroll
    for (int j = 0; j < 4; j++) {
        int idx = base + t * 4 + j;
        if (idx < N) g_offs[idx] = excl;
        excl += v[j];
    }
    if (t == 255) g_blksum[blockIdx.x] = wsum[7];
}

__global__ void scanB_kernel(int NB) {
    int t = threadIdx.x;  // 128 threads, NB <= 128
    __shared__ int ws[4];
    int v = (t < NB) ? g_blksum[t] : 0;
    int lane = t & 31, wid = t >> 5;
    int inc = v;
#pragma unroll
    for (int o = 1; o < 32; o <<= 1) {
        int y = __shfl_up_sync(0xffffffffu, inc, o);
        if (lane >= o) inc += y;
    }
    if (lane == 31) ws[wid] = inc;
    __syncthreads();
    int add = 0;
    for (int k = 0; k < wid; k++) add += ws[k];
    g_blkoff[t] = inc - v + add;
}

__global__ void scanC_kernel(int N, int E) {
    int i = blockIdx.x * blockDim.x + threadIdx.x;
    if (i < N) {
        int o = g_offs[i] + g_blkoff[i >> 10];
        g_offs[i] = o;
        g_cnt[i] = o;   // scatter cursor
    }
    if (i == 0) g_offs[N] = E;
}

__global__ void scatter_kernel(const int* __restrict__ ei, int E) {
    int e = blockIdx.x * blockDim.x + threadIdx.x;
    if (e >= E) return;
    int src = ei[e];
    int dst = ei[E + e];
    int pos = atomicAdd(&g_cnt[dst], 1);
    g_csr[pos] = src;
}

// ---------------------------------------------------------------------------
// Layer 0 linear: h = x(N,3) @ W0(3,64) -> g_hA; also s = h.as, d = h.ad
// ---------------------------------------------------------------------------
__global__ void lin0_kernel(const float* __restrict__ x,
                            const float* __restrict__ W0,
                            const float* __restrict__ as0,
                            const float* __restrict__ ad0, int N) {
    __shared__ float Ws[3 * 64];
    __shared__ float hs[64][65];
    int t = threadIdx.x;
    int c = t & 63, r = t >> 6;
    int n0 = blockIdx.x * 64;
    if (t < 192) Ws[t] = W0[t];
    __syncthreads();
#pragma unroll
    for (int i = 0; i < 16; i++) {
        int nl = r * 16 + i;
        int n = n0 + nl;
        float acc = 0.f;
        if (n < N) {
            float x0 = x[n * 3 + 0], x1 = x[n * 3 + 1], x2 = x[n * 3 + 2];
            acc = x0 * Ws[c] + x1 * Ws[64 + c] + x2 * Ws[128 + c];
            g_hA[n * 64 + c] = acc;
        }
        hs[nl][c] = acc;
    }
    __syncthreads();
    if (t < 64) {
        int n = n0 + t;
        if (n < N) {
            float sv = 0.f, dv = 0.f;
#pragma unroll
            for (int k = 0; k < 64; k++) {
                float hv = hs[t][k];
                sv += hv * as0[k];
                dv += hv * ad0[k];
            }
            g_s[n] = sv;
            g_d[n] = dv;
        }
    }
}

// ---------------------------------------------------------------------------
// Gather attention pass (g_hA -> g_hB): one warp per dst node.
//   num = p_self*h[dst] + sum_e p_e*h[src_e];  denom likewise
//   out[dst] = leaky_0.01(num/denom + bias)
// (max-shift skipped: softmax shift-invariant, logits are O(0.1))
// ---------------------------------------------------------------------------
__global__ void gather_kernel(const float* __restrict__ bias, int N) {
    int w = (blockIdx.x * blockDim.x + threadIdx.x) >> 5;
    int lane = threadIdx.x & 31;
    if (w >= N) return;
    int dst = w;
    float dv = g_d[dst];
    // self loop
    float lg = g_s[dst] + dv;
    lg = lg > 0.f ? lg : 0.2f * lg;
    float p = __expf(lg);
    float2 h2 = *(const float2*)(g_hA + dst * 64 + lane * 2);
    float ax = p * h2.x, ay = p * h2.y, den = p;
    int e = g_offs[dst], e1 = g_offs[dst + 1];
    for (; e + 1 < e1; e += 2) {
        int s0 = g_csr[e], s1 = g_csr[e + 1];
        float sv0 = g_s[s0], sv1 = g_s[s1];
        float2 ha = *(const float2*)(g_hA + s0 * 64 + lane * 2);
        float2 hb = *(const float2*)(g_hA + s1 * 64 + lane * 2);
        float l0 = sv0 + dv; l0 = l0 > 0.f ? l0 : 0.2f * l0;
        float l1 = sv1 + dv; l1 = l1 > 0.f ? l1 : 0.2f * l1;
        float p0 = __expf(l0), p1 = __expf(l1);
        ax += p0 * ha.x + p1 * hb.x;
        ay += p0 * ha.y + p1 * hb.y;
        den += p0 + p1;
    }
    if (e < e1) {
        int s0 = g_csr[e];
        float sv0 = g_s[s0];
        float2 ha = *(const float2*)(g_hA + s0 * 64 + lane * 2);
        float l0 = sv0 + dv; l0 = l0 > 0.f ? l0 : 0.2f * l0;
        float p0 = __expf(l0);
        ax += p0 * ha.x; ay += p0 * ha.y; den += p0;
    }
    float inv = 1.f / den;
    float ox = ax * inv + bias[lane * 2];
    float oy = ay * inv + bias[lane * 2 + 1];
    ox = ox > 0.f ? ox : 0.01f * ox;
    oy = oy > 0.f ? oy : 0.01f * oy;
    *(float2*)(g_hB + dst * 64 + lane * 2) = make_float2(ox, oy);
}

// ---------------------------------------------------------------------------
// GEMM (g_hB -> g_hA): h = x(128-node tile,64) @ W(64,64), 8x4 register tile;
// fused s/d attention dots via 16-lane shuffle reduction.
// Block: 256 threads = 16 node-groups x 16 col-groups.
// ---------------------------------------------------------------------------
__global__ void fin_lin_kernel(const float* __restrict__ W,
                               const float* __restrict__ avs,
                               const float* __restrict__ avd, int N) {
    __shared__ float xs[128][65];
    __shared__ float Ws[64][64];
    int t = threadIdx.x;
    int n0 = blockIdx.x * 128;
#pragma unroll
    for (int j = 0; j < 16; j++) {
        int idx = j * 256 + t;
        Ws[idx >> 6][idx & 63] = W[idx];
    }
#pragma unroll
    for (int j = 0; j < 32; j++) {
        int idx = j * 256 + t;
        int nl = idx >> 6, c = idx & 63;
        int n = n0 + nl;
        xs[nl][c] = (n < N) ? g_hB[n * 64 + c] : 0.f;
    }
    __syncthreads();
    int cg = t & 15, ng = t >> 4;
    float acc[8][4];
#pragma unroll
    for (int i = 0; i < 8; i++)
#pragma unroll
        for (int j = 0; j < 4; j++) acc[i][j] = 0.f;
#pragma unroll 8
    for (int k = 0; k < 64; k++) {
        float4 w4 = *(const float4*)&Ws[k][cg * 4];
#pragma unroll
        for (int i = 0; i < 8; i++) {
            float xv = xs[ng * 8 + i][k];
            acc[i][0] += xv * w4.x;
            acc[i][1] += xv * w4.y;
            acc[i][2] += xv * w4.z;
            acc[i][3] += xv * w4.w;
        }
    }
    // store h
#pragma unroll
    for (int i = 0; i < 8; i++) {
        int n = n0 + ng * 8 + i;
        if (n < N) {
            float4 o = make_float4(acc[i][0], acc[i][1], acc[i][2], acc[i][3]);
            *(float4*)(g_hA + n * 64 + cg * 4) = o;
        }
    }
    // fused s/d dots: partials over this thread's 4 cols, reduce over 16 lanes
    float a0 = avs[cg * 4], a1 = avs[cg * 4 + 1], a2 = avs[cg * 4 + 2], a3 = avs[cg * 4 + 3];
    float d0 = avd[cg * 4], d1 = avd[cg * 4 + 1], d2 = avd[cg * 4 + 2], d3 = avd[cg * 4 + 3];
#pragma unroll
    for (int i = 0; i < 8; i++) {
        float ps = acc[i][0] * a0 + acc[i][1] * a1 + acc[i][2] * a2 + acc[i][3] * a3;
        float pd = acc[i][0] * d0 + acc[i][1] * d1 + acc[i][2] * d2 + acc[i][3] * d3;
#pragma unroll
        for (int o = 8; o >= 1; o >>= 1) {
            ps += __shfl_xor_sync(0xffffffffu, ps, o, 16);
            pd += __shfl_xor_sync(0xffffffffu, pd, o, 16);
        }
        if (cg == 0) {
            int n = n0 + ng * 8 + i;
            if (n < N) { g_s[n] = ps; g_d[n] = pd; }
        }
    }
}

// ---------------------------------------------------------------------------
// Final stage (reads g_hB): out1 = h @ out_w + out_b (4x5 register tile);
// vn run-length pooling (batch sorted). Block: 128 nodes, 128 threads.
// ---------------------------------------------------------------------------
__global__ void fin_last_kernel(const float* __restrict__ out_w,
                                const float* __restrict__ out_b,
                                const int* __restrict__ batch,
                                float* __restrict__ out1, int N) {
    __shared__ float hs[128][65];
    __shared__ float ow[64][20];
    __shared__ float ob[20];
    __shared__ int bsh[128];
    int t = threadIdx.x;
    int n0 = blockIdx.x * 128;
    for (int idx = t; idx < 64 * 20; idx += 128) ow[idx / 20][idx % 20] = out_w[idx];
    if (t < 20) ob[t] = out_b[t];
#pragma unroll
    for (int j = 0; j < 64; j++) {
        int idx = j * 128 + t;
        int nl = idx >> 6, c = idx & 63;
        int n = n0 + nl;
        hs[nl][c] = (n < N) ? g_hB[n * 64 + c] : 0.f;
    }
    {
        int n = n0 + t;
        bsh[t] = (n < N) ? batch[n] : -1;
    }
    __syncthreads();
    int ngq = t >> 2, cgq = t & 3;   // 32 node groups x 4 col groups
    float acc[4][5];
#pragma unroll
    for (int i = 0; i < 4; i++)
#pragma unroll
        for (int j = 0; j < 5; j++) acc[i][j] = ob[cgq * 5 + j];
#pragma unroll 8
    for (int k = 0; k < 64; k++) {
        float wv[5];
#pragma unroll
        for (int j = 0; j < 5; j++) wv[j] = ow[k][cgq * 5 + j];
#pragma unroll
        for (int i = 0; i < 4; i++) {
            float hv = hs[ngq * 4 + i][k];
#pragma unroll
            for (int j = 0; j < 5; j++) acc[i][j] += hv * wv[j];
        }
    }
#pragma unroll
    for (int i = 0; i < 4; i++) {
        int n = n0 + ngq * 4 + i;
        if (n < N) {
#pragma unroll
            for (int j = 0; j < 5; j++) out1[n * 20 + cgq * 5 + j] = acc[i][j];
        }
    }
    // vn pooling: threads 0..63 own one column each, run-length over block
    if (t < 64) {
        int nend = N - n0;
        if (nend > 128) nend = 128;
        if (nend > 0) {
            int curg = bsh[0];
            float run = 0.f;
            for (int nl = 0; nl < nend; nl++) {
                int g = bsh[nl];
                if (g != curg) {
                    atomicAdd(&g_vnsum[curg * 64 + t], run);
                    run = 0.f;
                    curg = g;
                }
                run += hs[nl][t];
            }
            atomicAdd(&g_vnsum[curg * 64 + t], run);
        }
    }
}

// ---------------------------------------------------------------------------
// Virtual-node MLP head: 4 layers on [8,64] -> [8,20]. One block.
// ---------------------------------------------------------------------------
__global__ void vn_mlp_kernel(const float* __restrict__ vn_emb0,
                              const float* __restrict__ w1, const float* __restrict__ bb1,
                              const float* __restrict__ w2, const float* __restrict__ bb2,
                              const float* __restrict__ w3, const float* __restrict__ bb3,
                              const float* __restrict__ w4, const float* __restrict__ bb4,
                              float* __restrict__ outvn) {
    __shared__ float a[NGROUP][64], tmp[NGROUP][64];
    int t = threadIdx.x;  // 512
    int g = t >> 6, c = t & 63;
    a[g][c] = g_vnsum[g * 64 + c] + vn_emb0[c];
    __syncthreads();
    float s = bb1[c];
    for (int k = 0; k < 64; k++) s += a[g][k] * w1[k * 64 + c];
    tmp[g][c] = fmaxf(s, 0.f);
    __syncthreads();
    s = bb2[c];
    for (int k = 0; k < 64; k++) s += tmp[g][k] * w2[k * 64 + c];
    a[g][c] = fmaxf(s, 0.f);
    __syncthreads();
    s = bb3[c];
    for (int k = 0; k < 64; k++) s += a[g][k] * w3[k * 64 + c];
    tmp[g][c] = fmaxf(s, 0.f);
    __syncthreads();
    if (c < 20) {
        s = bb4[c];
        for (int k = 0; k < 64; k++) s += tmp[g][k] * w4[k * 20 + c];
        outvn[g * 20 + c] = fmaxf(s, 0.f);
    }
}

// ---------------------------------------------------------------------------
extern "C" void kernel_launch(void* const* d_in, const int* in_sizes, int n_in,
                              void* d_out, int out_size) {
    const float* x      = (const float*)d_in[0];
    const int*   ei     = (const int*)d_in[1];
    const int*   batch  = (const int*)d_in[2];
    const float* W0     = (const float*)d_in[3];
    const float* as0    = (const float*)d_in[4];
    const float* ad0    = (const float*)d_in[5];
    const float* b0     = (const float*)d_in[6];
    const float* W1     = (const float*)d_in[7];
    const float* as1    = (const float*)d_in[8];
    const float* ad1    = (const float*)d_in[9];
    const float* b1     = (const float*)d_in[10];
    const float* W2     = (const float*)d_in[11];
    const float* as2    = (const float*)d_in[12];
    const float* ad2    = (const float*)d_in[13];
    const float* b2     = (const float*)d_in[14];
    const float* vn_emb0= (const float*)d_in[15];
    const float* m1_w1  = (const float*)d_in[16];
    const float* m1_b1  = (const float*)d_in[17];
    const float* m1_w2  = (const float*)d_in[18];
    const float* m1_b2  = (const float*)d_in[19];
    const float* mf_w1  = (const float*)d_in[20];
    const float* mf_b1  = (const float*)d_in[21];
    const float* mf_w2  = (const float*)d_in[22];
    const float* mf_b2  = (const float*)d_in[23];
    const float* out_w  = (const float*)d_in[24];
    const float* out_b  = (const float*)d_in[25];

    int N = in_sizes[0] / 3;
    int E = in_sizes[1] / 2;
    float* out1 = (float*)d_out;
    float* outvn = out1 + (long long)N * 20;

    int nblk64  = (N + 63) / 64;
    int nblk128 = (N + 127) / 128;
    int eblk    = (E + 255) / 256;
    int NB      = (N + 1023) / 1024;
    int gblk    = (N * 32 + 255) / 256;

    // CSR build (graph shared by all 3 layers)
    zero_kernel<<<(N + 256) / 256, 256>>>(N);
    hist_kernel<<<eblk, 256>>>(ei, E);
    scanA_kernel<<<NB, 256>>>(N);
    scanB_kernel<<<1, 128>>>(NB);
    scanC_kernel<<<(N + 255) / 256, 256>>>(N, E);
    scatter_kernel<<<eblk, 256>>>(ei, E);

    // GNN layers (ping-pong: lin0 -> A, gather A->B, fin_lin B->A)
    lin0_kernel<<<nblk64, 256>>>(x, W0, as0, ad0, N);
    gather_kernel<<<gblk, 256>>>(b0, N);
    fin_lin_kernel<<<nblk128, 256>>>(W1, as1, ad1, N);
    gather_kernel<<<gblk, 256>>>(b1, N);
    fin_lin_kernel<<<nblk128, 256>>>(W2, as2, ad2, N);
    gather_kernel<<<gblk, 256>>>(b2, N);

    // heads (read g_hB)
    fin_last_kernel<<<nblk128, 128>>>(out_w, out_b, batch, out1, N);
    vn_mlp_kernel<<<1, 512>>>(vn_emb0, m1_w1, m1_b1, m1_w2, m1_b2,
                              mf_w1, mf_b1, mf_w2, mf_b2, outvn);
}

// round 4
// speedup vs baseline: 1.8249x; 1.0202x over previous
#include <cuda_runtime.h>
#include <cuda_fp16.h>

#define NMAX 100000
#define EMAX 1600000
#define HDIM 64
#define NGROUP 8

// ---------------- device scratch (no allocation allowed) --------------------
__device__ __align__(16) __half g_h16[NMAX * HDIM];  // fp16 mirror for gathers
__device__ __align__(16) float g_hB[NMAX * HDIM];    // fp32 gather output
__device__ float g_s[NMAX];
__device__ float g_d[NMAX];
__device__ int   g_cnt[NMAX + 1];     // histogram, later scatter cursor
__device__ int   g_offs[NMAX + 1];    // CSR row offsets (by dst)
__device__ int   g_blksum[256];
__device__ int   g_csr[EMAX];         // src indices sorted by dst
__device__ float g_vnsum[NGROUP * HDIM];

// ---------------------------------------------------------------------------
// CSR build: zero -> histogram -> scanA -> scanC(+blk prefix) -> scatter
// ---------------------------------------------------------------------------
__global__ void zero_kernel(int N) {
    int i = blockIdx.x * blockDim.x + threadIdx.x;
    if (i <= N) g_cnt[i] = 0;
    if (i < NGROUP * HDIM) g_vnsum[i] = 0.f;
}

__global__ void hist_kernel(const int* __restrict__ ei, int E) {
    int e = blockIdx.x * blockDim.x + threadIdx.x;
    if (e < E) atomicAdd(&g_cnt[ei[E + e]], 1);
}

// per-block exclusive scan of g_cnt (1024 elements / block of 256 threads)
__global__ void scanA_kernel(int N) {
    __shared__ int wsum[8];
    int t = threadIdx.x;
    int base = blockIdx.x * 1024;
    int v[4]; int s = 0;
#pragma unroll
    for (int j = 0; j < 4; j++) {
        int idx = base + t * 4 + j;
        v[j] = (idx < N) ? g_cnt[idx] : 0;
        s += v[j];
    }
    int lane = t & 31, wid = t >> 5;
    int inc = s;
#pragma unroll
    for (int o = 1; o < 32; o <<= 1) {
        int y = __shfl_up_sync(0xffffffffu, inc, o);
        if (lane >= o) inc += y;
    }
    if (lane == 31) wsum[wid] = inc;
    __syncthreads();
    if (t < 8) {
        int x = wsum[t];
#pragma unroll
        for (int o = 1; o < 8; o <<= 1) {
            int y = __shfl_up_sync(0xffu, x, o);
            if (t >= o) x += y;
        }
        wsum[t] = x;
    }
    __syncthreads();
    int excl = inc - s + (wid > 0 ? wsum[wid - 1] : 0);
#pragma unroll
    for (int j = 0; j < 4; j++) {
        int idx = base + t * 4 + j;
        if (idx < N) g_offs[idx] = excl;
        excl += v[j];
    }
    if (t == 255) g_blksum[blockIdx.x] = wsum[7];
}

// adds cross-block prefix (computed in-kernel by warp 0) and finalizes offsets
__global__ void scanC_kernel(int N, int E) {
    __shared__ int sbase;
    int myblk = (blockIdx.x * 256) >> 10;   // which scanA block this belongs to
    if (threadIdx.x < 32) {
        int acc = 0;
        for (int j = threadIdx.x; j < myblk; j += 32) acc += g_blksum[j];
#pragma unroll
        for (int o = 16; o >= 1; o >>= 1) acc += __shfl_xor_sync(0xffffffffu, acc, o);
        if (threadIdx.x == 0) sbase = acc;
    }
    __syncthreads();
    int i = blockIdx.x * 256 + threadIdx.x;
    if (i < N) {
        int o = g_offs[i] + sbase;
        g_offs[i] = o;
        g_cnt[i] = o;   // scatter cursor
    }
    if (i == 0) g_offs[N] = E;
}

__global__ void scatter_kernel(const int* __restrict__ ei, int E) {
    int e = blockIdx.x * blockDim.x + threadIdx.x;
    if (e >= E) return;
    int src = ei[e];
    int dst = ei[E + e];
    int pos = atomicAdd(&g_cnt[dst], 1);
    g_csr[pos] = src;
}

// ---------------------------------------------------------------------------
// Layer 0 linear: h = x(N,3) @ W0(3,64) -> g_h16; also s = h.as, d = h.ad
// ---------------------------------------------------------------------------
__global__ void lin0_kernel(const float* __restrict__ x,
                            const float* __restrict__ W0,
                            const float* __restrict__ as0,
                            const float* __restrict__ ad0, int N) {
    __shared__ float Ws[3 * 64];
    __shared__ float hs[64][65];
    int t = threadIdx.x;
    int c = t & 63, r = t >> 6;
    int n0 = blockIdx.x * 64;
    if (t < 192) Ws[t] = W0[t];
    __syncthreads();
#pragma unroll
    for (int i = 0; i < 16; i++) {
        int nl = r * 16 + i;
        int n = n0 + nl;
        float acc = 0.f;
        if (n < N) {
            float x0 = x[n * 3 + 0], x1 = x[n * 3 + 1], x2 = x[n * 3 + 2];
            acc = x0 * Ws[c] + x1 * Ws[64 + c] + x2 * Ws[128 + c];
            g_h16[n * 64 + c] = __float2half_rn(acc);
        }
        hs[nl][c] = acc;
    }
    __syncthreads();
    if (t < 64) {
        int n = n0 + t;
        if (n < N) {
            float sv = 0.f, dv = 0.f;
#pragma unroll
            for (int k = 0; k < 64; k++) {
                float hv = hs[t][k];
                sv += hv * as0[k];
                dv += hv * ad0[k];
            }
            g_s[n] = sv;
            g_d[n] = dv;
        }
    }
}

// ---------------------------------------------------------------------------
// Gather attention pass (g_h16 -> g_hB): one warp per dst node.
//   num = p_self*h[dst] + sum_e p_e*h[src_e];  denom likewise
//   out[dst] = leaky_0.01(num/denom + bias)
// (max-shift skipped: softmax shift-invariant, logits are O(0.1))
// ---------------------------------------------------------------------------
__global__ void gather_kernel(const float* __restrict__ bias, int N) {
    int w = (blockIdx.x * blockDim.x + threadIdx.x) >> 5;
    int lane = threadIdx.x & 31;
    if (w >= N) return;
    int dst = w;
    float dv = g_d[dst];
    // self loop
    float lg = g_s[dst] + dv;
    lg = lg > 0.f ? lg : 0.2f * lg;
    float p = __expf(lg);
    float2 h2 = __half22float2(*(const __half2*)(g_h16 + dst * 64 + lane * 2));
    float ax = p * h2.x, ay = p * h2.y, den = p;
    int e = g_offs[dst], e1 = g_offs[dst + 1];
    for (; e + 3 < e1; e += 4) {
        int s0 = g_csr[e], s1 = g_csr[e + 1], s2 = g_csr[e + 2], s3 = g_csr[e + 3];
        float sv0 = g_s[s0], sv1 = g_s[s1], sv2 = g_s[s2], sv3 = g_s[s3];
        float2 h0 = __half22float2(*(const __half2*)(g_h16 + s0 * 64 + lane * 2));
        float2 h1 = __half22float2(*(const __half2*)(g_h16 + s1 * 64 + lane * 2));
        float2 h2b = __half22float2(*(const __half2*)(g_h16 + s2 * 64 + lane * 2));
        float2 h3 = __half22float2(*(const __half2*)(g_h16 + s3 * 64 + lane * 2));
        float l0 = sv0 + dv; l0 = l0 > 0.f ? l0 : 0.2f * l0;
        float l1 = sv1 + dv; l1 = l1 > 0.f ? l1 : 0.2f * l1;
        float l2 = sv2 + dv; l2 = l2 > 0.f ? l2 : 0.2f * l2;
        float l3 = sv3 + dv; l3 = l3 > 0.f ? l3 : 0.2f * l3;
        float p0 = __expf(l0), p1 = __expf(l1), p2 = __expf(l2), p3 = __expf(l3);
        ax += p0 * h0.x + p1 * h1.x + p2 * h2b.x + p3 * h3.x;
        ay += p0 * h0.y + p1 * h1.y + p2 * h2b.y + p3 * h3.y;
        den += p0 + p1 + p2 + p3;
    }
    for (; e < e1; e++) {
        int s0 = g_csr[e];
        float sv0 = g_s[s0];
        float2 h0 = __half22float2(*(const __half2*)(g_h16 + s0 * 64 + lane * 2));
        float l0 = sv0 + dv; l0 = l0 > 0.f ? l0 : 0.2f * l0;
        float p0 = __expf(l0);
        ax += p0 * h0.x; ay += p0 * h0.y; den += p0;
    }
    float inv = 1.f / den;
    float ox = ax * inv + bias[lane * 2];
    float oy = ay * inv + bias[lane * 2 + 1];
    ox = ox > 0.f ? ox : 0.01f * ox;
    oy = oy > 0.f ? oy : 0.01f * oy;
    *(float2*)(g_hB + dst * 64 + lane * 2) = make_float2(ox, oy);
}

// ---------------------------------------------------------------------------
// GEMM (g_hB -> g_h16): h = x(128-node tile,64) @ W(64,64), 8x4 register tile;
// fused s/d attention dots via 16-lane shuffle reduction.
// Block: 256 threads = 16 node-groups x 16 col-groups.
// ---------------------------------------------------------------------------
__global__ void fin_lin_kernel(const float* __restrict__ W,
                               const float* __restrict__ avs,
                               const float* __restrict__ avd, int N) {
    __shared__ float xs[128][65];
    __shared__ float Ws[64][64];
    int t = threadIdx.x;
    int n0 = blockIdx.x * 128;
#pragma unroll
    for (int j = 0; j < 16; j++) {
        int idx = j * 256 + t;
        Ws[idx >> 6][idx & 63] = W[idx];
    }
#pragma unroll
    for (int j = 0; j < 32; j++) {
        int idx = j * 256 + t;
        int nl = idx >> 6, c = idx & 63;
        int n = n0 + nl;
        xs[nl][c] = (n < N) ? g_hB[n * 64 + c] : 0.f;
    }
    __syncthreads();
    int cg = t & 15, ng = t >> 4;
    float acc[8][4];
#pragma unroll
    for (int i = 0; i < 8; i++)
#pragma unroll
        for (int j = 0; j < 4; j++) acc[i][j] = 0.f;
#pragma unroll 8
    for (int k = 0; k < 64; k++) {
        float4 w4 = *(const float4*)&Ws[k][cg * 4];
#pragma unroll
        for (int i = 0; i < 8; i++) {
            float xv = xs[ng * 8 + i][k];
            acc[i][0] += xv * w4.x;
            acc[i][1] += xv * w4.y;
            acc[i][2] += xv * w4.z;
            acc[i][3] += xv * w4.w;
        }
    }
    // store fp16 mirror (only consumer is the next gather pass)
#pragma unroll
    for (int i = 0; i < 8; i++) {
        int n = n0 + ng * 8 + i;
        if (n < N) {
            __half2* hp = (__half2*)(g_h16 + n * 64 + cg * 4);
            hp[0] = __floats2half2_rn(acc[i][0], acc[i][1]);
            hp[1] = __floats2half2_rn(acc[i][2], acc[i][3]);
        }
    }
    // fused s/d dots: partials over this thread's 4 cols, reduce over 16 lanes
    float a0 = avs[cg * 4], a1 = avs[cg * 4 + 1], a2 = avs[cg * 4 + 2], a3 = avs[cg * 4 + 3];
    float d0 = avd[cg * 4], d1 = avd[cg * 4 + 1], d2 = avd[cg * 4 + 2], d3 = avd[cg * 4 + 3];
#pragma unroll
    for (int i = 0; i < 8; i++) {
        float ps = acc[i][0] * a0 + acc[i][1] * a1 + acc[i][2] * a2 + acc[i][3] * a3;
        float pd = acc[i][0] * d0 + acc[i][1] * d1 + acc[i][2] * d2 + acc[i][3] * d3;
#pragma unroll
        for (int o = 8; o >= 1; o >>= 1) {
            ps += __shfl_xor_sync(0xffffffffu, ps, o, 16);
            pd += __shfl_xor_sync(0xffffffffu, pd, o, 16);
        }
        if (cg == 0) {
            int n = n0 + ng * 8 + i;
            if (n < N) { g_s[n] = ps; g_d[n] = pd; }
        }
    }
}

// ---------------------------------------------------------------------------
// Final stage (reads g_hB): out1 = h @ out_w + out_b (4x5 register tile);
// vn run-length pooling (batch sorted). Block: 128 nodes, 128 threads.
// ---------------------------------------------------------------------------
__global__ void fin_last_kernel(const float* __restrict__ out_w,
                                const float* __restrict__ out_b,
                                const int* __restrict__ batch,
                                float* __restrict__ out1, int N) {
    __shared__ float hs[128][65];
    __shared__ float ow[64][20];
    __shared__ float ob[20];
    __shared__ int bsh[128];
    int t = threadIdx.x;
    int n0 = blockIdx.x * 128;
    for (int idx = t; idx < 64 * 20; idx += 128) ow[idx / 20][idx % 20] = out_w[idx];
    if (t < 20) ob[t] = out_b[t];
#pragma unroll
    for (int j = 0; j < 64; j++) {
        int idx = j * 128 + t;
        int nl = idx >> 6, c = idx & 63;
        int n = n0 + nl;
        hs[nl][c] = (n < N) ? g_hB[n * 64 + c] : 0.f;
    }
    {
        int n = n0 + t;
        bsh[t] = (n < N) ? batch[n] : -1;
    }
    __syncthreads();
    int ngq = t >> 2, cgq = t & 3;   // 32 node groups x 4 col groups
    float acc[4][5];
#pragma unroll
    for (int i = 0; i < 4; i++)
#pragma unroll
        for (int j = 0; j < 5; j++) acc[i][j] = ob[cgq * 5 + j];
#pragma unroll 8
    for (int k = 0; k < 64; k++) {
        float wv[5];
#pragma unroll
        for (int j = 0; j < 5; j++) wv[j] = ow[k][cgq * 5 + j];
#pragma unroll
        for (int i = 0; i < 4; i++) {
            float hv = hs[ngq * 4 + i][k];
#pragma unroll
            for (int j = 0; j < 5; j++) acc[i][j] += hv * wv[j];
        }
    }
#pragma unroll
    for (int i = 0; i < 4; i++) {
        int n = n0 + ngq * 4 + i;
        if (n < N) {
#pragma unroll
            for (int j = 0; j < 5; j++) out1[n * 20 + cgq * 5 + j] = acc[i][j];
        }
    }
    // vn pooling: threads 0..63 own one column each, run-length over block
    if (t < 64) {
        int nend = N - n0;
        if (nend > 128) nend = 128;
        if (nend > 0) {
            int curg = bsh[0];
            float run = 0.f;
            for (int nl = 0; nl < nend; nl++) {
                int g = bsh[nl];
                if (g != curg) {
                    atomicAdd(&g_vnsum[curg * 64 + t], run);
                    run = 0.f;
                    curg = g;
                }
                run += hs[nl][t];
            }
            atomicAdd(&g_vnsum[curg * 64 + t], run);
        }
    }
}

// ---------------------------------------------------------------------------
// Virtual-node MLP head: 4 layers on [8,64] -> [8,20]. One block.
// ---------------------------------------------------------------------------
__global__ void vn_mlp_kernel(const float* __restrict__ vn_emb0,
                              const float* __restrict__ w1, const float* __restrict__ bb1,
                              const float* __restrict__ w2, const float* __restrict__ bb2,
                              const float* __restrict__ w3, const float* __restrict__ bb3,
                              const float* __restrict__ w4, const float* __restrict__ bb4,
                              float* __restrict__ outvn) {
    __shared__ float a[NGROUP][64], tmp[NGROUP][64];
    int t = threadIdx.x;  // 512
    int g = t >> 6, c = t & 63;
    a[g][c] = g_vnsum[g * 64 + c] + vn_emb0[c];
    __syncthreads();
    float s = bb1[c];
    for (int k = 0; k < 64; k++) s += a[g][k] * w1[k * 64 + c];
    tmp[g][c] = fmaxf(s, 0.f);
    __syncthreads();
    s = bb2[c];
    for (int k = 0; k < 64; k++) s += tmp[g][k] * w2[k * 64 + c];
    a[g][c] = fmaxf(s, 0.f);
    __syncthreads();
    s = bb3[c];
    for (int k = 0; k < 64; k++) s += a[g][k] * w3[k * 64 + c];
    tmp[g][c] = fmaxf(s, 0.f);
    __syncthreads();
    if (c < 20) {
        s = bb4[c];
        for (int k = 0; k < 64; k++) s += tmp[g][k] * w4[k * 20 + c];
        outvn[g * 20 + c] = fmaxf(s, 0.f);
    }
}

// ---------------------------------------------------------------------------
extern "C" void kernel_launch(void* const* d_in, const int* in_sizes, int n_in,
                              void* d_out, int out_size) {
    const float* x      = (const float*)d_in[0];
    const int*   ei     = (const int*)d_in[1];
    const int*   batch  = (const int*)d_in[2];
    const float* W0     = (const float*)d_in[3];
    const float* as0    = (const float*)d_in[4];
    const float* ad0    = (const float*)d_in[5];
    const float* b0     = (const float*)d_in[6];
    const float* W1     = (const float*)d_in[7];
    const float* as1    = (const float*)d_in[8];
    const float* ad1    = (const float*)d_in[9];
    const float* b1     = (const float*)d_in[10];
    const float* W2     = (const float*)d_in[11];
    const float* as2    = (const float*)d_in[12];
    const float* ad2    = (const float*)d_in[13];
    const float* b2     = (const float*)d_in[14];
    const float* vn_emb0= (const float*)d_in[15];
    const float* m1_w1  = (const float*)d_in[16];
    const float* m1_b1  = (const float*)d_in[17];
    const float* m1_w2  = (const float*)d_in[18];
    const float* m1_b2  = (const float*)d_in[19];
    const float* mf_w1  = (const float*)d_in[20];
    const float* mf_b1  = (const float*)d_in[21];
    const float* mf_w2  = (const float*)d_in[22];
    const float* mf_b2  = (const float*)d_in[23];
    const float* out_w  = (const float*)d_in[24];
    const float* out_b  = (const float*)d_in[25];

    int N = in_sizes[0] / 3;
    int E = in_sizes[1] / 2;
    float* out1 = (float*)d_out;
    float* outvn = out1 + (long long)N * 20;

    int nblk64  = (N + 63) / 64;
    int nblk128 = (N + 127) / 128;
    int eblk    = (E + 255) / 256;
    int NB      = (N + 1023) / 1024;
    int gblk    = (N * 32 + 255) / 256;

    // CSR build (graph shared by all 3 layers)
    zero_kernel<<<(N + 256) / 256, 256>>>(N);
    hist_kernel<<<eblk, 256>>>(ei, E);
    scanA_kernel<<<NB, 256>>>(N);
    scanC_kernel<<<(N + 255) / 256, 256>>>(N, E);
    scatter_kernel<<<eblk, 256>>>(ei, E);

    // GNN layers (ping-pong: lin0 -> h16, gather h16->B, fin_lin B->h16)
    lin0_kernel<<<nblk64, 256>>>(x, W0, as0, ad0, N);
    gather_kernel<<<gblk, 256>>>(b0, N);
    fin_lin_kernel<<<nblk128, 256>>>(W1, as1, ad1, N);
    gather_kernel<<<gblk, 256>>>(b1, N);
    fin_lin_kernel<<<nblk128, 256>>>(W2, as2, ad2, N);
    gather_kernel<<<gblk, 256>>>(b2, N);

    // heads (read g_hB)
    fin_last_kernel<<<nblk128, 128>>>(out_w, out_b, batch, out1, N);
    vn_mlp_kernel<<<1, 512>>>(vn_emb0, m1_w1, m1_b1, m1_w2, m1_b2,
                              mf_w1, mf_b1, mf_w2, mf_b2, outvn);
}

// round 5
// speedup vs baseline: 2.1028x; 1.1523x over previous
#include <cuda_runtime.h>
#include <cuda_fp16.h>

#define NMAX 100000
#define EMAX 1600000
#define HDIM 64
#define NGROUP 8

// ---------------- device scratch (no allocation allowed) --------------------
__device__ __align__(256) __half g_h16[NMAX * HDIM];  // fp16 mirror for gathers
__device__ __align__(256) float g_hB[NMAX * HDIM];    // fp32 gather output
__device__ float g_s[NMAX];
__device__ float g_d[NMAX];
__device__ int   g_cnt[NMAX + 1];     // histogram, later scatter cursor
__device__ int   g_offs[NMAX + 1];    // CSR row offsets (by dst)
__device__ int   g_blksum[256];
__device__ int   g_csr[EMAX];         // src indices sorted by dst
__device__ float g_vnsum[NGROUP * HDIM];

// ---------------------------------------------------------------------------
// CSR build: zero -> histogram -> scanA -> scanC(+blk prefix) -> scatter
// ---------------------------------------------------------------------------
__global__ void zero_kernel(int N) {
    int i = blockIdx.x * blockDim.x + threadIdx.x;
    if (i <= N) g_cnt[i] = 0;
    if (i < NGROUP * HDIM) g_vnsum[i] = 0.f;
}

__global__ void hist_kernel(const int* __restrict__ ei, int E) {
    int e = blockIdx.x * blockDim.x + threadIdx.x;
    if (e < E) atomicAdd(&g_cnt[ei[E + e]], 1);
}

// per-block exclusive scan of g_cnt (1024 elements / block of 256 threads)
__global__ void scanA_kernel(int N) {
    __shared__ int wsum[8];
    int t = threadIdx.x;
    int base = blockIdx.x * 1024;
    int v[4]; int s = 0;
#pragma unroll
    for (int j = 0; j < 4; j++) {
        int idx = base + t * 4 + j;
        v[j] = (idx < N) ? g_cnt[idx] : 0;
        s += v[j];
    }
    int lane = t & 31, wid = t >> 5;
    int inc = s;
#pragma unroll
    for (int o = 1; o < 32; o <<= 1) {
        int y = __shfl_up_sync(0xffffffffu, inc, o);
        if (lane >= o) inc += y;
    }
    if (lane == 31) wsum[wid] = inc;
    __syncthreads();
    if (t < 8) {
        int x = wsum[t];
#pragma unroll
        for (int o = 1; o < 8; o <<= 1) {
            int y = __shfl_up_sync(0xffu, x, o);
            if (t >= o) x += y;
        }
        wsum[t] = x;
    }
    __syncthreads();
    int excl = inc - s + (wid > 0 ? wsum[wid - 1] : 0);
#pragma unroll
    for (int j = 0; j < 4; j++) {
        int idx = base + t * 4 + j;
        if (idx < N) g_offs[idx] = excl;
        excl += v[j];
    }
    if (t == 255) g_blksum[blockIdx.x] = wsum[7];
}

// adds cross-block prefix (computed in-kernel by warp 0) and finalizes offsets
__global__ void scanC_kernel(int N, int E) {
    __shared__ int sbase;
    int myblk = (blockIdx.x * 256) >> 10;   // which scanA block this belongs to
    if (threadIdx.x < 32) {
        int acc = 0;
        for (int j = threadIdx.x; j < myblk; j += 32) acc += g_blksum[j];
#pragma unroll
        for (int o = 16; o >= 1; o >>= 1) acc += __shfl_xor_sync(0xffffffffu, acc, o);
        if (threadIdx.x == 0) sbase = acc;
    }
    __syncthreads();
    int i = blockIdx.x * 256 + threadIdx.x;
    if (i < N) {
        int o = g_offs[i] + sbase;
        g_offs[i] = o;
        g_cnt[i] = o;   // scatter cursor
    }
    if (i == 0) g_offs[N] = E;
}

__global__ void scatter_kernel(const int* __restrict__ ei, int E) {
    int e = blockIdx.x * blockDim.x + threadIdx.x;
    if (e >= E) return;
    int src = ei[e];
    int dst = ei[E + e];
    int pos = atomicAdd(&g_cnt[dst], 1);
    g_csr[pos] = src;
}

// ---------------------------------------------------------------------------
// Layer 0 linear: h = x(N,3) @ W0(3,64) -> g_h16; also s = h.as, d = h.ad
// ---------------------------------------------------------------------------
__global__ void lin0_kernel(const float* __restrict__ x,
                            const float* __restrict__ W0,
                            const float* __restrict__ as0,
                            const float* __restrict__ ad0, int N) {
    __shared__ float Ws[3 * 64];
    __shared__ float hs[64][65];
    int t = threadIdx.x;
    int c = t & 63, r = t >> 6;
    int n0 = blockIdx.x * 64;
    if (t < 192) Ws[t] = W0[t];
    __syncthreads();
#pragma unroll
    for (int i = 0; i < 16; i++) {
        int nl = r * 16 + i;
        int n = n0 + nl;
        float acc = 0.f;
        if (n < N) {
            float x0 = x[n * 3 + 0], x1 = x[n * 3 + 1], x2 = x[n * 3 + 2];
            acc = x0 * Ws[c] + x1 * Ws[64 + c] + x2 * Ws[128 + c];
            g_h16[n * 64 + c] = __float2half_rn(acc);
        }
        hs[nl][c] = acc;
    }
    __syncthreads();
    if (t < 64) {
        int n = n0 + t;
        if (n < N) {
            float sv = 0.f, dv = 0.f;
#pragma unroll
            for (int k = 0; k < 64; k++) {
                float hv = hs[t][k];
                sv += hv * as0[k];
                dv += hv * ad0[k];
            }
            g_s[n] = sv;
            g_d[n] = dv;
        }
    }
}

// ---------------------------------------------------------------------------
// Gather attention pass (g_h16 -> g_hB): one warp per dst node.
// Chunked: each lane computes p for ONE edge (1 coalesced csr LDG, 1 s LDG,
// 1 MUFU per 32 edges), stages (src,p) in smem; broadcast loop then does
// 1 LDS.64 + 1 LDG per edge. Per-lane denom, one butterfly reduce at end.
// (max-shift skipped: softmax shift-invariant, logits are O(0.1))
// ---------------------------------------------------------------------------
__global__ void gather_kernel(const float* __restrict__ bias, int N) {
    __shared__ int2 stage[8][32];
    int w = (blockIdx.x * blockDim.x + threadIdx.x) >> 5;
    int lane = threadIdx.x & 31;
    int wl = threadIdx.x >> 5;
    if (w >= N) return;
    int dst = w;
    float dv = g_d[dst];
    // self loop
    float lg = g_s[dst] + dv;
    lg = lg > 0.f ? lg : 0.2f * lg;
    float pself = __expf(lg);
    float2 h2 = __half22float2(*(const __half2*)(g_h16 + dst * 64 + lane * 2));
    float ax = pself * h2.x, ay = pself * h2.y;
    float denl = (lane == 0) ? pself : 0.f;
    int e0 = g_offs[dst], e1 = g_offs[dst + 1];
    for (int base = e0; base < e1; base += 32) {
        int cnt = e1 - base;
        if (cnt > 32) cnt = 32;
        int idx = 0;
        float pv = 0.f;
        if (lane < cnt) {
            idx = g_csr[base + lane];
            float sv = g_s[idx];
            float l = sv + dv;
            l = l > 0.f ? l : 0.2f * l;
            pv = __expf(l);
        }
        denl += pv;
        stage[wl][lane] = make_int2(idx, __float_as_int(pv));
        __syncwarp();
        int j = 0;
        for (; j + 3 < cnt; j += 4) {
            int2 v0 = stage[wl][j], v1 = stage[wl][j + 1];
            int2 v2 = stage[wl][j + 2], v3 = stage[wl][j + 3];
            float2 f0 = __half22float2(*(const __half2*)(g_h16 + v0.x * 64 + lane * 2));
            float2 f1 = __half22float2(*(const __half2*)(g_h16 + v1.x * 64 + lane * 2));
            float2 f2 = __half22float2(*(const __half2*)(g_h16 + v2.x * 64 + lane * 2));
            float2 f3 = __half22float2(*(const __half2*)(g_h16 + v3.x * 64 + lane * 2));
            float p0 = __int_as_float(v0.y), p1 = __int_as_float(v1.y);
            float p2 = __int_as_float(v2.y), p3 = __int_as_float(v3.y);
            ax += p0 * f0.x + p1 * f1.x + p2 * f2.x + p3 * f3.x;
            ay += p0 * f0.y + p1 * f1.y + p2 * f2.y + p3 * f3.y;
        }
        for (; j < cnt; j++) {
            int2 v = stage[wl][j];
            float2 f = __half22float2(*(const __half2*)(g_h16 + v.x * 64 + lane * 2));
            float pj = __int_as_float(v.y);
            ax += pj * f.x;
            ay += pj * f.y;
        }
        __syncwarp();
    }
#pragma unroll
    for (int o = 16; o >= 1; o >>= 1) denl += __shfl_xor_sync(0xffffffffu, denl, o);
    float inv = 1.f / denl;
    float ox = ax * inv + bias[lane * 2];
    float oy = ay * inv + bias[lane * 2 + 1];
    ox = ox > 0.f ? ox : 0.01f * ox;
    oy = oy > 0.f ? oy : 0.01f * oy;
    *(float2*)(g_hB + dst * 64 + lane * 2) = make_float2(ox, oy);
}

// ---------------------------------------------------------------------------
// GEMM (g_hB -> g_h16): h = x(128-node tile,64) @ W(64,64), 8x4 register tile;
// fused s/d attention dots via 16-lane shuffle reduction.
// Block: 256 threads = 16 node-groups x 16 col-groups.
// ---------------------------------------------------------------------------
__global__ void fin_lin_kernel(const float* __restrict__ W,
                               const float* __restrict__ avs,
                               const float* __restrict__ avd, int N) {
    __shared__ float xs[128][65];
    __shared__ float Ws[64][64];
    int t = threadIdx.x;
    int n0 = blockIdx.x * 128;
#pragma unroll
    for (int j = 0; j < 16; j++) {
        int idx = j * 256 + t;
        Ws[idx >> 6][idx & 63] = W[idx];
    }
#pragma unroll
    for (int j = 0; j < 32; j++) {
        int idx = j * 256 + t;
        int nl = idx >> 6, c = idx & 63;
        int n = n0 + nl;
        xs[nl][c] = (n < N) ? g_hB[n * 64 + c] : 0.f;
    }
    __syncthreads();
    int cg = t & 15, ng = t >> 4;
    float acc[8][4];
#pragma unroll
    for (int i = 0; i < 8; i++)
#pragma unroll
        for (int j = 0; j < 4; j++) acc[i][j] = 0.f;
#pragma unroll 8
    for (int k = 0; k < 64; k++) {
        float4 w4 = *(const float4*)&Ws[k][cg * 4];
#pragma unroll
        for (int i = 0; i < 8; i++) {
            float xv = xs[ng * 8 + i][k];
            acc[i][0] += xv * w4.x;
            acc[i][1] += xv * w4.y;
            acc[i][2] += xv * w4.z;
            acc[i][3] += xv * w4.w;
        }
    }
    // store fp16 mirror (only consumer is the next gather pass)
#pragma unroll
    for (int i = 0; i < 8; i++) {
        int n = n0 + ng * 8 + i;
        if (n < N) {
            __half2* hp = (__half2*)(g_h16 + n * 64 + cg * 4);
            hp[0] = __floats2half2_rn(acc[i][0], acc[i][1]);
            hp[1] = __floats2half2_rn(acc[i][2], acc[i][3]);
        }
    }
    // fused s/d dots: partials over this thread's 4 cols, reduce over 16 lanes
    float a0 = avs[cg * 4], a1 = avs[cg * 4 + 1], a2 = avs[cg * 4 + 2], a3 = avs[cg * 4 + 3];
    float d0 = avd[cg * 4], d1 = avd[cg * 4 + 1], d2 = avd[cg * 4 + 2], d3 = avd[cg * 4 + 3];
#pragma unroll
    for (int i = 0; i < 8; i++) {
        float ps = acc[i][0] * a0 + acc[i][1] * a1 + acc[i][2] * a2 + acc[i][3] * a3;
        float pd = acc[i][0] * d0 + acc[i][1] * d1 + acc[i][2] * d2 + acc[i][3] * d3;
#pragma unroll
        for (int o = 8; o >= 1; o >>= 1) {
            ps += __shfl_xor_sync(0xffffffffu, ps, o, 16);
            pd += __shfl_xor_sync(0xffffffffu, pd, o, 16);
        }
        if (cg == 0) {
            int n = n0 + ng * 8 + i;
            if (n < N) { g_s[n] = ps; g_d[n] = pd; }
        }
    }
}

// ---------------------------------------------------------------------------
// Final stage (reads g_hB): out1 = h @ out_w + out_b (4x5 register tile);
// vn run-length pooling (batch sorted). Block: 128 nodes, 128 threads.
// ---------------------------------------------------------------------------
__global__ void fin_last_kernel(const float* __restrict__ out_w,
                                const float* __restrict__ out_b,
                                const int* __restrict__ batch,
                                float* __restrict__ out1, int N) {
    __shared__ float hs[128][65];
    __shared__ float ow[64][20];
    __shared__ float ob[20];
    __shared__ int bsh[128];
    int t = threadIdx.x;
    int n0 = blockIdx.x * 128;
    for (int idx = t; idx < 64 * 20; idx += 128) ow[idx / 20][idx % 20] = out_w[idx];
    if (t < 20) ob[t] = out_b[t];
#pragma unroll
    for (int j = 0; j < 64; j++) {
        int idx = j * 128 + t;
        int nl = idx >> 6, c = idx & 63;
        int n = n0 + nl;
        hs[nl][c] = (n < N) ? g_hB[n * 64 + c] : 0.f;
    }
    {
        int n = n0 + t;
        bsh[t] = (n < N) ? batch[n] : -1;
    }
    __syncthreads();
    int ngq = t >> 2, cgq = t & 3;   // 32 node groups x 4 col groups
    float acc[4][5];
#pragma unroll
    for (int i = 0; i < 4; i++)
#pragma unroll
        for (int j = 0; j < 5; j++) acc[i][j] = ob[cgq * 5 + j];
#pragma unroll 8
    for (int k = 0; k < 64; k++) {
        float wv[5];
#pragma unroll
        for (int j = 0; j < 5; j++) wv[j] = ow[k][cgq * 5 + j];
#pragma unroll
        for (int i = 0; i < 4; i++) {
            float hv = hs[ngq * 4 + i][k];
#pragma unroll
            for (int j = 0; j < 5; j++) acc[i][j] += hv * wv[j];
        }
    }
#pragma unroll
    for (int i = 0; i < 4; i++) {
        int n = n0 + ngq * 4 + i;
        if (n < N) {
#pragma unroll
            for (int j = 0; j < 5; j++) out1[n * 20 + cgq * 5 + j] = acc[i][j];
        }
    }
    // vn pooling: threads 0..63 own one column each, run-length over block
    if (t < 64) {
        int nend = N - n0;
        if (nend > 128) nend = 128;
        if (nend > 0) {
            int curg = bsh[0];
            float run = 0.f;
            for (int nl = 0; nl < nend; nl++) {
                int g = bsh[nl];
                if (g != curg) {
                    atomicAdd(&g_vnsum[curg * 64 + t], run);
                    run = 0.f;
                    curg = g;
                }
                run += hs[nl][t];
            }
            atomicAdd(&g_vnsum[curg * 64 + t], run);
        }
    }
}

// ---------------------------------------------------------------------------
// Virtual-node MLP head: 4 layers on [8,64] -> [8,20]. One block.
// ---------------------------------------------------------------------------
__global__ void vn_mlp_kernel(const float* __restrict__ vn_emb0,
                              const float* __restrict__ w1, const float* __restrict__ bb1,
                              const float* __restrict__ w2, const float* __restrict__ bb2,
                              const float* __restrict__ w3, const float* __restrict__ bb3,
                              const float* __restrict__ w4, const float* __restrict__ bb4,
                              float* __restrict__ outvn) {
    __shared__ float a[NGROUP][64], tmp[NGROUP][64];
    int t = threadIdx.x;  // 512
    int g = t >> 6, c = t & 63;
    a[g][c] = g_vnsum[g * 64 + c] + vn_emb0[c];
    __syncthreads();
    float s = bb1[c];
    for (int k = 0; k < 64; k++) s += a[g][k] * w1[k * 64 + c];
    tmp[g][c] = fmaxf(s, 0.f);
    __syncthreads();
    s = bb2[c];
    for (int k = 0; k < 64; k++) s += tmp[g][k] * w2[k * 64 + c];
    a[g][c] = fmaxf(s, 0.f);
    __syncthreads();
    s = bb3[c];
    for (int k = 0; k < 64; k++) s += a[g][k] * w3[k * 64 + c];
    tmp[g][c] = fmaxf(s, 0.f);
    __syncthreads();
    if (c < 20) {
        s = bb4[c];
        for (int k = 0; k < 64; k++) s += tmp[g][k] * w4[k * 20 + c];
        outvn[g * 20 + c] = fmaxf(s, 0.f);
    }
}

// ---------------------------------------------------------------------------
extern "C" void kernel_launch(void* const* d_in, const int* in_sizes, int n_in,
                              void* d_out, int out_size) {
    const float* x      = (const float*)d_in[0];
    const int*   ei     = (const int*)d_in[1];
    const int*   batch  = (const int*)d_in[2];
    const float* W0     = (const float*)d_in[3];
    const float* as0    = (const float*)d_in[4];
    const float* ad0    = (const float*)d_in[5];
    const float* b0     = (const float*)d_in[6];
    const float* W1     = (const float*)d_in[7];
    const float* as1    = (const float*)d_in[8];
    const float* ad1    = (const float*)d_in[9];
    const float* b1     = (const float*)d_in[10];
    const float* W2     = (const float*)d_in[11];
    const float* as2    = (const float*)d_in[12];
    const float* ad2    = (const float*)d_in[13];
    const float* b2     = (const float*)d_in[14];
    const float* vn_emb0= (const float*)d_in[15];
    const float* m1_w1  = (const float*)d_in[16];
    const float* m1_b1  = (const float*)d_in[17];
    const float* m1_w2  = (const float*)d_in[18];
    const float* m1_b2  = (const float*)d_in[19];
    const float* mf_w1  = (const float*)d_in[20];
    const float* mf_b1  = (const float*)d_in[21];
    const float* mf_w2  = (const float*)d_in[22];
    const float* mf_b2  = (const float*)d_in[23];
    const float* out_w  = (const float*)d_in[24];
    const float* out_b  = (const float*)d_in[25];

    int N = in_sizes[0] / 3;
    int E = in_sizes[1] / 2;
    float* out1 = (float*)d_out;
    float* outvn = out1 + (long long)N * 20;

    int nblk64  = (N + 63) / 64;
    int nblk128 = (N + 127) / 128;
    int eblk    = (E + 255) / 256;
    int NB      = (N + 1023) / 1024;
    int gblk    = (N * 32 + 255) / 256;

    // CSR build (graph shared by all 3 layers)
    zero_kernel<<<(N + 256) / 256, 256>>>(N);
    hist_kernel<<<eblk, 256>>>(ei, E);
    scanA_kernel<<<NB, 256>>>(N);
    scanC_kernel<<<(N + 255) / 256, 256>>>(N, E);
    scatter_kernel<<<eblk, 256>>>(ei, E);

    // GNN layers (ping-pong: lin0 -> h16, gather h16->B, fin_lin B->h16)
    lin0_kernel<<<nblk64, 256>>>(x, W0, as0, ad0, N);
    gather_kernel<<<gblk, 256>>>(b0, N);
    fin_lin_kernel<<<nblk128, 256>>>(W1, as1, ad1, N);
    gather_kernel<<<gblk, 256>>>(b1, N);
    fin_lin_kernel<<<nblk128, 256>>>(W2, as2, ad2, N);
    gather_kernel<<<gblk, 256>>>(b2, N);

    // heads (read g_hB)
    fin_last_kernel<<<nblk128, 128>>>(out_w, out_b, batch, out1, N);
    vn_mlp_kernel<<<1, 512>>>(vn_emb0, m1_w1, m1_b1, m1_w2, m1_b2,
                              mf_w1, mf_b1, mf_w2, mf_b2, outvn);
}